// round 1
// baseline (speedup 1.0000x reference)
#include <cuda_runtime.h>

// Problem constants (fixed by the dataset)
#define BB 4
#define SS 4096
#define DD 512
#define HH 64
#define NROW (BB * SS)   // 16384

// Scratch (device globals; no allocation allowed)
__device__ float g_Q[NROW * HH];
__device__ float g_K[NROW * HH];
__device__ float g_V[NROW * HH];
__device__ float g_O[NROW * HH];

__device__ __forceinline__ void fma4x4(float (&acc)[4][4], float4 a, float4 b) {
    float av[4] = {a.x, a.y, a.z, a.w};
    float bv[4] = {b.x, b.y, b.z, b.w};
#pragma unroll
    for (int i = 0; i < 4; i++)
#pragma unroll
        for (int j = 0; j < 4; j++)
            acc[i][j] = fmaf(av[i], bv[j], acc[i][j]);
}

// ============================================================================
// Kernel 1: QKV projections.  out = x @ W + b for W in {Wq, Wk, Wv}.
// GEMM M=16384 N=64 K=512; tile 64x64, K-chunk 32; 256 thr, 4x4 frags.
// Ak is k-major ([kk][r]) so fragments load as float4 along rows.
// ============================================================================
__global__ __launch_bounds__(256) void qkv_kernel(
    const float* __restrict__ x,
    const float* __restrict__ Wq, const float* __restrict__ bq,
    const float* __restrict__ Wk, const float* __restrict__ bk,
    const float* __restrict__ Wv, const float* __restrict__ bv)
{
    __shared__ float Ak[32][68];   // Ak[kk][r] : x tile, k-major
    __shared__ float Bs[32][68];   // Bs[kk][n] : W tile

    const float* W; const float* bias; float* out;
    int which = blockIdx.y;
    if (which == 0)      { W = Wq; bias = bq; out = g_Q; }
    else if (which == 1) { W = Wk; bias = bk; out = g_K; }
    else                 { W = Wv; bias = bv; out = g_V; }

    int row0 = blockIdx.x * 64;
    int t = threadIdx.x, ty = t >> 4, tx = t & 15;
    float acc[4][4] = {};

    for (int k0 = 0; k0 < DD; k0 += 32) {
#pragma unroll
        for (int l = 0; l < 2; l++) {                 // x tile: 64 rows x 32 k
            int idx = t + l * 256;                    // 0..511
            int r = idx >> 3, c4 = idx & 7;
            float4 v = *(const float4*)(x + (size_t)(row0 + r) * DD + k0 + c4 * 4);
            Ak[c4 * 4 + 0][r] = v.x; Ak[c4 * 4 + 1][r] = v.y;
            Ak[c4 * 4 + 2][r] = v.z; Ak[c4 * 4 + 3][r] = v.w;
        }
#pragma unroll
        for (int l = 0; l < 2; l++) {                 // W tile: 32 k x 64 n
            int idx = t + l * 256;
            int kk = idx >> 4, c4 = idx & 15;
            *(float4*)&Bs[kk][c4 * 4] =
                *(const float4*)(W + (size_t)(k0 + kk) * HH + c4 * 4);
        }
        __syncthreads();
#pragma unroll
        for (int kk = 0; kk < 32; kk++) {
            float4 a = *(float4*)&Ak[kk][ty * 4];
            float4 b = *(float4*)&Bs[kk][tx * 4];
            fma4x4(acc, a, b);
        }
        __syncthreads();
    }
#pragma unroll
    for (int i = 0; i < 4; i++)
#pragma unroll
        for (int j = 0; j < 4; j++)
            out[(size_t)(row0 + ty * 4 + i) * HH + tx * 4 + j] =
                acc[i][j] + bias[tx * 4 + j];
}

// ============================================================================
// Kernel 2: causal flash attention, head dim 64.
// Each block handles TWO row tiles: mt = bx and mt = 63-bx  -> exactly 65
// j-tile units of work per block (perfect causal load balance).
// Shared layouts chosen so every mainloop operand is an LDS.128:
//   Qd[d][q], Kd[d][k]  (d-major, for S = Q K^T)
//   Pk[k][q], Vs[k][d]  (for O += P V)
// All rows padded to 68 floats (bank-conflict-free).
// ============================================================================
__global__ __launch_bounds__(256) void flash_kernel()
{
    extern __shared__ float sm[];
    float* Qd = sm;                 // [64][68]
    float* Kd = sm + 64 * 68;       // [64][68]
    float* Vs = sm + 2 * 64 * 68;   // [64][68]
    float* Pk = sm + 3 * 64 * 68;   // [64][68]

    int b = blockIdx.y;
    int t = threadIdx.x, ty = t >> 4, tx = t & 15;
    const float scale = 0.015625f;  // 1/sqrt(4096)

    for (int half = 0; half < 2; half++) {
        int mt = (half == 0) ? (int)blockIdx.x : 63 - (int)blockIdx.x;
        int q0 = mt * 64;

        // Load Q tile (d-major)
        const float* Qg = g_Q + ((size_t)b * SS + q0) * HH;
#pragma unroll
        for (int l = 0; l < 4; l++) {
            int idx = t + l * 256;
            int r = idx >> 4, c4 = idx & 15;
            float4 v = *(const float4*)(Qg + r * HH + c4 * 4);
            Qd[(c4 * 4 + 0) * 68 + r] = v.x; Qd[(c4 * 4 + 1) * 68 + r] = v.y;
            Qd[(c4 * 4 + 2) * 68 + r] = v.z; Qd[(c4 * 4 + 3) * 68 + r] = v.w;
        }

        float m_run[4], l_run[4], acc[4][4];
#pragma unroll
        for (int i = 0; i < 4; i++) {
            m_run[i] = -1e30f; l_run[i] = 0.f;
#pragma unroll
            for (int j = 0; j < 4; j++) acc[i][j] = 0.f;
        }
        __syncthreads();

        for (int jt = 0; jt <= mt; jt++) {
            int k0 = jt * 64;
            const float* Kg = g_K + ((size_t)b * SS + k0) * HH;
            const float* Vg = g_V + ((size_t)b * SS + k0) * HH;
#pragma unroll
            for (int l = 0; l < 4; l++) {
                int idx = t + l * 256;
                int r = idx >> 4, c4 = idx & 15;
                float4 kv = *(const float4*)(Kg + r * HH + c4 * 4);
                Kd[(c4 * 4 + 0) * 68 + r] = kv.x; Kd[(c4 * 4 + 1) * 68 + r] = kv.y;
                Kd[(c4 * 4 + 2) * 68 + r] = kv.z; Kd[(c4 * 4 + 3) * 68 + r] = kv.w;
                *(float4*)&Vs[r * 68 + c4 * 4] = *(const float4*)(Vg + r * HH + c4 * 4);
            }
            __syncthreads();

            // S = Q K^T  (64 d-steps, fragments 4x4)
            float s[4][4] = {};
#pragma unroll 8
            for (int d = 0; d < 64; d++) {
                float4 a  = *(float4*)&Qd[d * 68 + ty * 4];
                float4 bb = *(float4*)&Kd[d * 68 + tx * 4];
                fma4x4(s, a, bb);
            }

            // scale + causal mask (only diagonal tile needs masking)
            if (jt == mt) {
#pragma unroll
                for (int i = 0; i < 4; i++)
#pragma unroll
                    for (int j = 0; j < 4; j++) {
                        int kg = k0 + tx * 4 + j, qg = q0 + ty * 4 + i;
                        s[i][j] = (kg > qg) ? -1e30f : s[i][j] * scale;
                    }
            } else {
#pragma unroll
                for (int i = 0; i < 4; i++)
#pragma unroll
                    for (int j = 0; j < 4; j++) s[i][j] *= scale;
            }

            // online softmax: rows owned by 16 tx-lanes -> shfl allreduce width 16
            float p[4][4];
#pragma unroll
            for (int i = 0; i < 4; i++) {
                float mx = fmaxf(fmaxf(s[i][0], s[i][1]), fmaxf(s[i][2], s[i][3]));
                mx = fmaxf(mx, __shfl_xor_sync(0xffffffffu, mx, 1));
                mx = fmaxf(mx, __shfl_xor_sync(0xffffffffu, mx, 2));
                mx = fmaxf(mx, __shfl_xor_sync(0xffffffffu, mx, 4));
                mx = fmaxf(mx, __shfl_xor_sync(0xffffffffu, mx, 8));
                float mnew = fmaxf(m_run[i], mx);
                float alpha = __expf(m_run[i] - mnew);
                float rs = 0.f;
#pragma unroll
                for (int j = 0; j < 4; j++) {
                    p[i][j] = __expf(s[i][j] - mnew);
                    rs += p[i][j];
                }
                rs += __shfl_xor_sync(0xffffffffu, rs, 1);
                rs += __shfl_xor_sync(0xffffffffu, rs, 2);
                rs += __shfl_xor_sync(0xffffffffu, rs, 4);
                rs += __shfl_xor_sync(0xffffffffu, rs, 8);
                l_run[i] = l_run[i] * alpha + rs;
                m_run[i] = mnew;
#pragma unroll
                for (int j = 0; j < 4; j++) acc[i][j] *= alpha;
            }

            // stash P transposed (k-major) for the PV GEMM
#pragma unroll
            for (int i = 0; i < 4; i++)
#pragma unroll
                for (int j = 0; j < 4; j++)
                    Pk[(tx * 4 + j) * 68 + ty * 4 + i] = p[i][j];
            __syncthreads();

            // O += P V
#pragma unroll 8
            for (int kk = 0; kk < 64; kk++) {
                float4 a  = *(float4*)&Pk[kk * 68 + ty * 4];
                float4 bb = *(float4*)&Vs[kk * 68 + tx * 4];
                fma4x4(acc, a, bb);
            }
            __syncthreads();
        }

        // epilogue: normalize, store
#pragma unroll
        for (int i = 0; i < 4; i++) {
            float inv = 1.f / l_run[i];
#pragma unroll
            for (int j = 0; j < 4; j++)
                g_O[((size_t)b * SS + q0 + ty * 4 + i) * HH + tx * 4 + j] =
                    acc[i][j] * inv;
        }
    }
}

// ============================================================================
// Kernel 3: output projection.  out = O @ Wo + bo.
// GEMM M=16384 N=512 K=64; tile 64x64, single K pass.
// ============================================================================
__global__ __launch_bounds__(256) void outproj_kernel(
    const float* __restrict__ Wo, const float* __restrict__ bo,
    float* __restrict__ out)
{
    __shared__ float Ok[64][68];   // Ok[k][r]  (k-major attn-out tile)
    __shared__ float Ws[64][68];   // Ws[k][n]

    int row0 = blockIdx.x * 64, n0 = blockIdx.y * 64;
    int t = threadIdx.x, ty = t >> 4, tx = t & 15;

#pragma unroll
    for (int l = 0; l < 4; l++) {
        int idx = t + l * 256;
        int r = idx >> 4, c4 = idx & 15;
        float4 v = *(const float4*)(g_O + (size_t)(row0 + r) * HH + c4 * 4);
        Ok[c4 * 4 + 0][r] = v.x; Ok[c4 * 4 + 1][r] = v.y;
        Ok[c4 * 4 + 2][r] = v.z; Ok[c4 * 4 + 3][r] = v.w;
        *(float4*)&Ws[r][c4 * 4] =
            *(const float4*)(Wo + (size_t)r * DD + n0 + c4 * 4);
    }
    __syncthreads();

    float acc[4][4] = {};
#pragma unroll 8
    for (int kk = 0; kk < 64; kk++) {
        float4 a  = *(float4*)&Ok[kk][ty * 4];
        float4 bb = *(float4*)&Ws[kk][tx * 4];
        fma4x4(acc, a, bb);
    }
#pragma unroll
    for (int i = 0; i < 4; i++)
#pragma unroll
        for (int j = 0; j < 4; j++)
            out[(size_t)(row0 + ty * 4 + i) * DD + n0 + tx * 4 + j] =
                acc[i][j] + bo[n0 + tx * 4 + j];
}

// ============================================================================
extern "C" void kernel_launch(void* const* d_in, const int* in_sizes, int n_in,
                              void* d_out, int out_size)
{
    const float* x  = (const float*)d_in[0];
    const float* Wq = (const float*)d_in[1];
    const float* bq = (const float*)d_in[2];
    const float* Wk = (const float*)d_in[3];
    const float* bk = (const float*)d_in[4];
    const float* Wv = (const float*)d_in[5];
    const float* bv = (const float*)d_in[6];
    const float* Wo = (const float*)d_in[7];
    const float* bo = (const float*)d_in[8];
    float* out = (float*)d_out;

    qkv_kernel<<<dim3(NROW / 64, 3), 256>>>(x, Wq, bq, Wk, bk, Wv, bv);

    size_t shmem = 4 * 64 * 68 * sizeof(float);   // 69632 B
    cudaFuncSetAttribute(flash_kernel,
                         cudaFuncAttributeMaxDynamicSharedMemorySize, (int)shmem);
    flash_kernel<<<dim3(32, BB), 256, shmem>>>();

    outproj_kernel<<<dim3(NROW / 64, DD / 64), 256>>>(Wo, bo, out);
}

// round 2
// speedup vs baseline: 1.6719x; 1.6719x over previous
#include <cuda_runtime.h>

// Problem constants (fixed by the dataset)
#define BB 4
#define SS 4096
#define DD 512
#define HH 64
#define NROW (BB * SS)   // 16384

// Scratch (device globals; no allocation allowed)
__device__ float g_Q[NROW * HH];
__device__ float g_K[NROW * HH];
__device__ float g_V[NROW * HH];
__device__ float g_O[NROW * HH];

__device__ __forceinline__ void fma4x4(float (&acc)[4][4], float4 a, float4 b) {
    float av[4] = {a.x, a.y, a.z, a.w};
    float bv[4] = {b.x, b.y, b.z, b.w};
#pragma unroll
    for (int i = 0; i < 4; i++)
#pragma unroll
        for (int j = 0; j < 4; j++)
            acc[i][j] = fmaf(av[i], bv[j], acc[i][j]);
}

// tf32 helpers
__device__ __forceinline__ unsigned f2tf32(float f) {
    unsigned u;
    asm("cvt.rna.tf32.f32 %0, %1;" : "=r"(u) : "f"(f));
    return u;
}

__device__ __forceinline__ void mma_tf32(float (&d)[4], const unsigned (&a)[4],
                                         const unsigned (&b)[2]) {
    asm volatile(
        "mma.sync.aligned.m16n8k8.row.col.f32.tf32.tf32.f32 "
        "{%0,%1,%2,%3}, {%4,%5,%6,%7}, {%8,%9}, {%0,%1,%2,%3};"
        : "+f"(d[0]), "+f"(d[1]), "+f"(d[2]), "+f"(d[3])
        : "r"(a[0]), "r"(a[1]), "r"(a[2]), "r"(a[3]), "r"(b[0]), "r"(b[1]));
}

// ============================================================================
// Kernel 1: QKV projections (fp32 FFMA — exact).
// ============================================================================
__global__ __launch_bounds__(256) void qkv_kernel(
    const float* __restrict__ x,
    const float* __restrict__ Wq, const float* __restrict__ bq,
    const float* __restrict__ Wk, const float* __restrict__ bk,
    const float* __restrict__ Wv, const float* __restrict__ bv)
{
    __shared__ float Ak[32][68];
    __shared__ float Bs[32][68];

    const float* W; const float* bias; float* out;
    int which = blockIdx.y;
    if (which == 0)      { W = Wq; bias = bq; out = g_Q; }
    else if (which == 1) { W = Wk; bias = bk; out = g_K; }
    else                 { W = Wv; bias = bv; out = g_V; }

    int row0 = blockIdx.x * 64;
    int t = threadIdx.x, ty = t >> 4, tx = t & 15;
    float acc[4][4] = {};

    for (int k0 = 0; k0 < DD; k0 += 32) {
#pragma unroll
        for (int l = 0; l < 2; l++) {
            int idx = t + l * 256;
            int r = idx >> 3, c4 = idx & 7;
            float4 v = *(const float4*)(x + (size_t)(row0 + r) * DD + k0 + c4 * 4);
            Ak[c4 * 4 + 0][r] = v.x; Ak[c4 * 4 + 1][r] = v.y;
            Ak[c4 * 4 + 2][r] = v.z; Ak[c4 * 4 + 3][r] = v.w;
        }
#pragma unroll
        for (int l = 0; l < 2; l++) {
            int idx = t + l * 256;
            int kk = idx >> 4, c4 = idx & 15;
            *(float4*)&Bs[kk][c4 * 4] =
                *(const float4*)(W + (size_t)(k0 + kk) * HH + c4 * 4);
        }
        __syncthreads();
#pragma unroll
        for (int kk = 0; kk < 32; kk++) {
            float4 a = *(float4*)&Ak[kk][ty * 4];
            float4 b = *(float4*)&Bs[kk][tx * 4];
            fma4x4(acc, a, b);
        }
        __syncthreads();
    }
#pragma unroll
    for (int i = 0; i < 4; i++)
#pragma unroll
        for (int j = 0; j < 4; j++)
            out[(size_t)(row0 + ty * 4 + i) * HH + tx * 4 + j] =
                acc[i][j] + bias[tx * 4 + j];
}

// ============================================================================
// Kernel 2: causal flash attention via tf32 mma.sync (tensor pipe).
// 64x64 tiles, 128 threads / 4 warps; warp w owns rows [16w,16w+16) x all 64
// cols, so softmax reduces are 2 in-quad shfls.
//
// GEMM1 (S=QK^T) uses a permuted-k fragment mapping: logical mma k-slot l<4
// is sourced only from threads lane%4==l, so each thread may privately own a
// contiguous physical-k range -> A/B fragments load as LDS.128 (stride-80
// rows, bank-free: (4*ln4 + qd) mod 8 per phase).
// GEMM2 (O+=PV) uses the standard mapping with scalar LDS:
//   Ps stride 68 -> bank (4*ln4+qd)%32 distinct; Vs stride 72 -> (8qd+ln4).
// ============================================================================
__global__ __launch_bounds__(128) void flash_tf32_kernel()
{
    extern __shared__ float sm[];
    float* Qs = sm;                      // 64 x 80
    float* Ks = sm + 64 * 80;            // 64 x 80
    float* Ps = sm + 2 * 64 * 80;        // 64 x 68
    float* Vs = sm + 2 * 64 * 80 + 64 * 68; // 64 x 72

    const int t    = threadIdx.x;
    const int w    = t >> 5;
    const int lane = t & 31;
    const int qd   = lane & 3;   // quad index (logical k-slot owner)
    const int ln4  = lane >> 2;  // 0..7
    const int b    = blockIdx.y;
    const int mt   = 63 - (int)blockIdx.x;   // big tiles first
    const int q0   = mt * 64;
    const float scale = 0.015625f;           // 1/sqrt(4096)
    const int rowA = 16 * w + ln4;

    // ---- load Q tile (raw fp32 bits; HMMA truncates to tf32) ----
    {
        const float* Qg = g_Q + ((size_t)b * SS + q0) * HH;
#pragma unroll
        for (int l = 0; l < 8; l++) {
            int u = t + l * 128;
            int r = u >> 4, c4 = u & 15;
            *(float4*)&Qs[r * 80 + c4 * 4] =
                *(const float4*)(Qg + r * HH + c4 * 4);
        }
    }

    float o_acc[8][4];
    float m_run[2] = {-1e30f, -1e30f};
    float l_run[2] = {0.f, 0.f};
#pragma unroll
    for (int nt = 0; nt < 8; nt++)
#pragma unroll
        for (int v = 0; v < 4; v++) o_acc[nt][v] = 0.f;

    for (int jt = 0; jt <= mt; jt++) {
        __syncthreads();   // previous iteration's smem reads complete
        {
            const float* Kg = g_K + ((size_t)b * SS + jt * 64) * HH;
            const float* Vg = g_V + ((size_t)b * SS + jt * 64) * HH;
#pragma unroll
            for (int l = 0; l < 8; l++) {
                int u = t + l * 128;
                int r = u >> 4, c4 = u & 15;
                *(float4*)&Ks[r * 80 + c4 * 4] =
                    *(const float4*)(Kg + r * HH + c4 * 4);
                float4 vv = *(const float4*)(Vg + r * HH + c4 * 4);
                float4 cv;
                cv.x = __uint_as_float(f2tf32(vv.x));
                cv.y = __uint_as_float(f2tf32(vv.y));
                cv.z = __uint_as_float(f2tf32(vv.z));
                cv.w = __uint_as_float(f2tf32(vv.w));
                *(float4*)&Vs[r * 72 + c4 * 4] = cv;
            }
        }
        __syncthreads();

        // ---- GEMM1: S = Q K^T (permuted-k, vectorized fragment loads) ----
        float s_acc[8][4];
#pragma unroll
        for (int nt = 0; nt < 8; nt++)
#pragma unroll
            for (int v = 0; v < 4; v++) s_acc[nt][v] = 0.f;

#pragma unroll
        for (int jj = 0; jj < 4; jj++) {
            int ub = (qd + 4 * jj) * 4;   // this thread's 4-float physical-k unit
            float4 fA = *(float4*)&Qs[rowA * 80 + ub];
            float4 fB = *(float4*)&Qs[(rowA + 8) * 80 + ub];
            unsigned a0[4] = {__float_as_uint(fA.x), __float_as_uint(fB.x),
                              __float_as_uint(fA.y), __float_as_uint(fB.y)};
            unsigned a1[4] = {__float_as_uint(fA.z), __float_as_uint(fB.z),
                              __float_as_uint(fA.w), __float_as_uint(fB.w)};
#pragma unroll
            for (int nt = 0; nt < 8; nt++) {
                float4 fK = *(float4*)&Ks[(8 * nt + ln4) * 80 + ub];
                unsigned b0[2] = {__float_as_uint(fK.x), __float_as_uint(fK.y)};
                unsigned b1[2] = {__float_as_uint(fK.z), __float_as_uint(fK.w)};
                mma_tf32(s_acc[nt], a0, b0);
                mma_tf32(s_acc[nt], a1, b1);
            }
        }

        // ---- scale + causal mask (diagonal tile only) ----
        if (jt == mt) {
#pragma unroll
            for (int nt = 0; nt < 8; nt++)
#pragma unroll
                for (int v = 0; v < 4; v++) {
                    int row = rowA + ((v >= 2) ? 8 : 0);          // local row
                    int col = 8 * nt + 2 * qd + (v & 1);          // local col
                    s_acc[nt][v] = (col > row) ? -1e30f : s_acc[nt][v] * scale;
                }
        } else {
#pragma unroll
            for (int nt = 0; nt < 8; nt++)
#pragma unroll
                for (int v = 0; v < 4; v++) s_acc[nt][v] *= scale;
        }

        // ---- online softmax (per thread: two rows rowA, rowA+8) ----
#pragma unroll
        for (int rr = 0; rr < 2; rr++) {
            float mx = -1e30f;
#pragma unroll
            for (int nt = 0; nt < 8; nt++)
                mx = fmaxf(mx, fmaxf(s_acc[nt][2 * rr], s_acc[nt][2 * rr + 1]));
            mx = fmaxf(mx, __shfl_xor_sync(0xffffffffu, mx, 1));
            mx = fmaxf(mx, __shfl_xor_sync(0xffffffffu, mx, 2));
            float mnew  = fmaxf(m_run[rr], mx);
            float alpha = __expf(m_run[rr] - mnew);
            float rs = 0.f;
#pragma unroll
            for (int nt = 0; nt < 8; nt++) {
                float p0 = __expf(s_acc[nt][2 * rr]     - mnew);
                float p1 = __expf(s_acc[nt][2 * rr + 1] - mnew);
                rs += p0 + p1;
                s_acc[nt][2 * rr]     = p0;
                s_acc[nt][2 * rr + 1] = p1;
            }
            rs += __shfl_xor_sync(0xffffffffu, rs, 1);
            rs += __shfl_xor_sync(0xffffffffu, rs, 2);
            l_run[rr] = l_run[rr] * alpha + rs;
            m_run[rr] = mnew;
#pragma unroll
            for (int nt = 0; nt < 8; nt++) {
                o_acc[nt][2 * rr]     *= alpha;
                o_acc[nt][2 * rr + 1] *= alpha;
            }
        }

        // ---- stash P (tf32-rounded) for the PV mma ----
#pragma unroll
        for (int nt = 0; nt < 8; nt++) {
            float2 p0, p1;
            p0.x = __uint_as_float(f2tf32(s_acc[nt][0]));
            p0.y = __uint_as_float(f2tf32(s_acc[nt][1]));
            p1.x = __uint_as_float(f2tf32(s_acc[nt][2]));
            p1.y = __uint_as_float(f2tf32(s_acc[nt][3]));
            *(float2*)&Ps[rowA * 68 + 8 * nt + 2 * qd]       = p0;
            *(float2*)&Ps[(rowA + 8) * 68 + 8 * nt + 2 * qd] = p1;
        }
        __syncwarp();

        // ---- GEMM2: O += P V (standard mapping, scalar bank-free LDS) ----
#pragma unroll
        for (int j = 0; j < 8; j++) {
            int k0 = 8 * j;
            unsigned a[4];
            a[0] = __float_as_uint(Ps[rowA * 68 + k0 + qd]);
            a[1] = __float_as_uint(Ps[(rowA + 8) * 68 + k0 + qd]);
            a[2] = __float_as_uint(Ps[rowA * 68 + k0 + qd + 4]);
            a[3] = __float_as_uint(Ps[(rowA + 8) * 68 + k0 + qd + 4]);
#pragma unroll
            for (int nt = 0; nt < 8; nt++) {
                unsigned bb[2];
                bb[0] = __float_as_uint(Vs[(k0 + qd) * 72 + 8 * nt + ln4]);
                bb[1] = __float_as_uint(Vs[(k0 + qd + 4) * 72 + 8 * nt + ln4]);
                mma_tf32(o_acc[nt], a, bb);
            }
        }
    }

    // ---- epilogue: normalize and store ----
    float inv0 = 1.f / l_run[0];
    float inv1 = 1.f / l_run[1];
    float* Og = g_O + ((size_t)b * SS + q0) * HH;
#pragma unroll
    for (int nt = 0; nt < 8; nt++) {
        float2 o0, o1;
        o0.x = o_acc[nt][0] * inv0; o0.y = o_acc[nt][1] * inv0;
        o1.x = o_acc[nt][2] * inv1; o1.y = o_acc[nt][3] * inv1;
        *(float2*)&Og[rowA * HH + 8 * nt + 2 * qd]       = o0;
        *(float2*)&Og[(rowA + 8) * HH + 8 * nt + 2 * qd] = o1;
    }
}

// ============================================================================
// Kernel 3: output projection (fp32 FFMA — exact).
// ============================================================================
__global__ __launch_bounds__(256) void outproj_kernel(
    const float* __restrict__ Wo, const float* __restrict__ bo,
    float* __restrict__ out)
{
    __shared__ float Ok[64][68];
    __shared__ float Ws[64][68];

    int row0 = blockIdx.x * 64, n0 = blockIdx.y * 64;
    int t = threadIdx.x, ty = t >> 4, tx = t & 15;

#pragma unroll
    for (int l = 0; l < 4; l++) {
        int idx = t + l * 256;
        int r = idx >> 4, c4 = idx & 15;
        float4 v = *(const float4*)(g_O + (size_t)(row0 + r) * HH + c4 * 4);
        Ok[c4 * 4 + 0][r] = v.x; Ok[c4 * 4 + 1][r] = v.y;
        Ok[c4 * 4 + 2][r] = v.z; Ok[c4 * 4 + 3][r] = v.w;
        *(float4*)&Ws[r][c4 * 4] =
            *(const float4*)(Wo + (size_t)r * DD + n0 + c4 * 4);
    }
    __syncthreads();

    float acc[4][4] = {};
#pragma unroll 8
    for (int kk = 0; kk < 64; kk++) {
        float4 a  = *(float4*)&Ok[kk][ty * 4];
        float4 bb = *(float4*)&Ws[kk][tx * 4];
        fma4x4(acc, a, bb);
    }
#pragma unroll
    for (int i = 0; i < 4; i++)
#pragma unroll
        for (int j = 0; j < 4; j++)
            out[(size_t)(row0 + ty * 4 + i) * DD + n0 + tx * 4 + j] =
                acc[i][j] + bo[n0 + tx * 4 + j];
}

// ============================================================================
extern "C" void kernel_launch(void* const* d_in, const int* in_sizes, int n_in,
                              void* d_out, int out_size)
{
    const float* x  = (const float*)d_in[0];
    const float* Wq = (const float*)d_in[1];
    const float* bq = (const float*)d_in[2];
    const float* Wk = (const float*)d_in[3];
    const float* bk = (const float*)d_in[4];
    const float* Wv = (const float*)d_in[5];
    const float* bv = (const float*)d_in[6];
    const float* Wo = (const float*)d_in[7];
    const float* bo = (const float*)d_in[8];
    float* out = (float*)d_out;

    qkv_kernel<<<dim3(NROW / 64, 3), 256>>>(x, Wq, bq, Wk, bk, Wv, bv);

    size_t shmem = (size_t)(64 * 80 + 64 * 80 + 64 * 68 + 64 * 72) * sizeof(float); // 76800
    static int attr_set = 0;
    if (!attr_set) {
        cudaFuncSetAttribute(flash_tf32_kernel,
                             cudaFuncAttributeMaxDynamicSharedMemorySize, (int)shmem);
        attr_set = 1;
    }
    flash_tf32_kernel<<<dim3(64, BB), 128, shmem>>>();

    outproj_kernel<<<dim3(NROW / 64, DD / 64), 256>>>(Wo, bo, out);
}

// round 4
// speedup vs baseline: 1.9303x; 1.1546x over previous
#include <cuda_runtime.h>

#define BB 4
#define SS 4096
#define DD 512
#define HH 64
#define NROW (BB * SS)   // 16384

__device__ float g_Q[NROW * HH];
__device__ float g_K[NROW * HH];
__device__ float g_V[NROW * HH];
__device__ float g_O[NROW * HH];
__device__ unsigned g_ctr;

__device__ __forceinline__ unsigned f2tf32(float f) {
    unsigned u;
    asm("cvt.rna.tf32.f32 %0, %1;" : "=r"(u) : "f"(f));
    return u;
}
__device__ __forceinline__ float rne(float f) { return __uint_as_float(f2tf32(f)); }

__device__ __forceinline__ void mma_tf32(float (&d)[4], const unsigned (&a)[4],
                                         const unsigned (&b)[2]) {
    asm volatile(
        "mma.sync.aligned.m16n8k8.row.col.f32.tf32.tf32.f32 "
        "{%0,%1,%2,%3}, {%4,%5,%6,%7}, {%8,%9}, {%0,%1,%2,%3};"
        : "+f"(d[0]), "+f"(d[1]), "+f"(d[2]), "+f"(d[3])
        : "r"(a[0]), "r"(a[1]), "r"(a[2]), "r"(a[3]), "r"(b[0]), "r"(b[1]));
}
#define FU __float_as_uint

// ============================================================================
// Kernel 1: QKV projections, tf32 mma.  C[16384,64] = x @ W + b, 3 weights.
// Block: 128 thr / 4 warps, M-tile 128 (warp m32), K-chunks of 64.
// Xs [128][80]: k-contiguous rows  -> conflict-free LDS.128 A fragments.
// Ws [64][70]:  untransposed [k][n] -> scalar B loads, stride 70 conflict-free.
// ============================================================================
__global__ __launch_bounds__(128) void qkv_tf32_kernel(
    const float* __restrict__ x,
    const float* __restrict__ Wq, const float* __restrict__ bq,
    const float* __restrict__ Wk, const float* __restrict__ bk,
    const float* __restrict__ Wv, const float* __restrict__ bv)
{
    extern __shared__ float sm[];
    float* Xs = sm;              // 128 x 80
    float* Ws = sm + 128 * 80;   // 64 x 70

    const float* W; const float* bias; float* out;
    int which = blockIdx.y;
    if (which == 0)      { W = Wq; bias = bq; out = g_Q; }
    else if (which == 1) { W = Wk; bias = bk; out = g_K; }
    else                 { W = Wv; bias = bv; out = g_V; }

    // reset the flash work-queue counter (qkv always precedes flash in-stream)
    if (blockIdx.x == 0 && which == 0 && threadIdx.x == 0) g_ctr = 0u;

    const int row0 = blockIdx.x * 128;
    const int t = threadIdx.x, w = t >> 5, lane = t & 31;
    const int qd = lane & 3, ln4 = lane >> 2;
    const int rowA = 32 * w + ln4;

    float acc[2][8][4];
#pragma unroll
    for (int mf = 0; mf < 2; mf++)
#pragma unroll
        for (int nt = 0; nt < 8; nt++)
#pragma unroll
            for (int v = 0; v < 4; v++) acc[mf][nt][v] = 0.f;

    for (int k0 = 0; k0 < DD; k0 += 64) {
        __syncthreads();
#pragma unroll
        for (int l = 0; l < 16; l++) {           // x tile 128 x 64
            int u = t + l * 128;
            int r = u >> 4, c4 = u & 15;
            float4 v = *(const float4*)(x + (size_t)(row0 + r) * DD + k0 + c4 * 4);
            v.x = rne(v.x); v.y = rne(v.y); v.z = rne(v.z); v.w = rne(v.w);
            *(float4*)&Xs[r * 80 + c4 * 4] = v;
        }
#pragma unroll
        for (int l = 0; l < 8; l++) {            // W tile 64 x 64 (k-major rows)
            int u = t + l * 128;
            int kk = u >> 4, c4 = u & 15;
            float4 v = *(const float4*)(W + (size_t)(k0 + kk) * HH + c4 * 4);
            float2 lo = {rne(v.x), rne(v.y)}, hi = {rne(v.z), rne(v.w)};
            *(float2*)&Ws[kk * 70 + c4 * 4]     = lo;
            *(float2*)&Ws[kk * 70 + c4 * 4 + 2] = hi;
        }
        __syncthreads();

#pragma unroll
        for (int jj = 0; jj < 4; jj++) {
            int ub = (qd + 4 * jj) * 4;
            float4 f0 = *(float4*)&Xs[rowA * 80 + ub];
            float4 f1 = *(float4*)&Xs[(rowA + 8) * 80 + ub];
            float4 f2 = *(float4*)&Xs[(rowA + 16) * 80 + ub];
            float4 f3 = *(float4*)&Xs[(rowA + 24) * 80 + ub];
            unsigned a00[4] = {FU(f0.x), FU(f1.x), FU(f0.y), FU(f1.y)};
            unsigned a01[4] = {FU(f0.z), FU(f1.z), FU(f0.w), FU(f1.w)};
            unsigned a10[4] = {FU(f2.x), FU(f3.x), FU(f2.y), FU(f3.y)};
            unsigned a11[4] = {FU(f2.z), FU(f3.z), FU(f2.w), FU(f3.w)};
#pragma unroll
            for (int nt = 0; nt < 8; nt++) {
                int c = 8 * nt + ln4;
                unsigned b0[2] = {FU(Ws[(ub + 0) * 70 + c]), FU(Ws[(ub + 1) * 70 + c])};
                unsigned b1[2] = {FU(Ws[(ub + 2) * 70 + c]), FU(Ws[(ub + 3) * 70 + c])};
                mma_tf32(acc[0][nt], a00, b0);
                mma_tf32(acc[0][nt], a01, b1);
                mma_tf32(acc[1][nt], a10, b0);
                mma_tf32(acc[1][nt], a11, b1);
            }
        }
    }

#pragma unroll
    for (int mf = 0; mf < 2; mf++)
#pragma unroll
        for (int nt = 0; nt < 8; nt++) {
            int c = 8 * nt + 2 * qd;
            int row = row0 + rowA + 16 * mf;
            float b0 = bias[c], b1 = bias[c + 1];
            float2 v0 = {acc[mf][nt][0] + b0, acc[mf][nt][1] + b1};
            float2 v1 = {acc[mf][nt][2] + b0, acc[mf][nt][3] + b1};
            *(float2*)(out + (size_t)row * HH + c)       = v0;
            *(float2*)(out + (size_t)(row + 8) * HH + c) = v1;
        }
}

// ============================================================================
// Kernel 2: causal flash attention, tf32 mma, persistent LPT work queue.
// Grid 296 (2 blocks/SM); tiles dispensed big-first via atomic counter.
// GEMM1: Qs/Ks stride 80 (conflict-free LDS.128 both operands).
// GEMM2: Ps stride 80 (vector A frags), Vs stride 70 (conflict-free scalar B).
// ============================================================================
__global__ __launch_bounds__(128) void flash_tf32_kernel()
{
    extern __shared__ float sm[];
    float* Qs = sm;                   // 64 x 80
    float* Ks = sm + 64 * 80;         // 64 x 80
    float* Ps = sm + 2 * 64 * 80;     // 64 x 80
    float* Vs = sm + 3 * 64 * 80;     // 64 x 70
    __shared__ unsigned s_tile;

    const int t = threadIdx.x, w = t >> 5, lane = t & 31;
    const int qd = lane & 3, ln4 = lane >> 2;
    const int rowA = 16 * w + ln4;
    const float scale = 0.015625f;    // 1/sqrt(4096)

    while (true) {
        if (t == 0) s_tile = atomicAdd(&g_ctr, 1u);
        __syncthreads();              // broadcast + protect smem from prev tile
        unsigned i = s_tile;
        if (i >= 256u) break;
        const int mt = 63 - (int)(i >> 2);   // biggest tiles first (LPT)
        const int b  = (int)(i & 3u);
        const int q0 = mt * 64;

        const float* Qg = g_Q + ((size_t)b * SS + q0) * HH;
#pragma unroll
        for (int l = 0; l < 8; l++) {
            int u = t + l * 128;
            int r = u >> 4, c4 = u & 15;
            *(float4*)&Qs[r * 80 + c4 * 4] = *(const float4*)(Qg + r * HH + c4 * 4);
        }

        float o_acc[8][4];
        float m_run[2] = {-1e30f, -1e30f};
        float l_run[2] = {0.f, 0.f};
#pragma unroll
        for (int nt = 0; nt < 8; nt++)
#pragma unroll
            for (int v = 0; v < 4; v++) o_acc[nt][v] = 0.f;

        for (int jt = 0; jt <= mt; jt++) {
            __syncthreads();
            {
                const float* Kg = g_K + ((size_t)b * SS + jt * 64) * HH;
                const float* Vg = g_V + ((size_t)b * SS + jt * 64) * HH;
#pragma unroll
                for (int l = 0; l < 8; l++) {
                    int u = t + l * 128;
                    int r = u >> 4, c4 = u & 15;
                    *(float4*)&Ks[r * 80 + c4 * 4] =
                        *(const float4*)(Kg + r * HH + c4 * 4);
                    float4 vv = *(const float4*)(Vg + r * HH + c4 * 4);
                    float2 lo = {rne(vv.x), rne(vv.y)}, hi = {rne(vv.z), rne(vv.w)};
                    *(float2*)&Vs[r * 70 + c4 * 4]     = lo;
                    *(float2*)&Vs[r * 70 + c4 * 4 + 2] = hi;
                }
            }
            __syncthreads();

            // ---- GEMM1: S = Q K^T ----
            float s_acc[8][4];
#pragma unroll
            for (int nt = 0; nt < 8; nt++)
#pragma unroll
                for (int v = 0; v < 4; v++) s_acc[nt][v] = 0.f;

#pragma unroll
            for (int jj = 0; jj < 4; jj++) {
                int ub = (qd + 4 * jj) * 4;
                float4 fA = *(float4*)&Qs[rowA * 80 + ub];
                float4 fB = *(float4*)&Qs[(rowA + 8) * 80 + ub];
                unsigned a0[4] = {FU(fA.x), FU(fB.x), FU(fA.y), FU(fB.y)};
                unsigned a1[4] = {FU(fA.z), FU(fB.z), FU(fA.w), FU(fB.w)};
#pragma unroll
                for (int nt = 0; nt < 8; nt++) {
                    float4 fK = *(float4*)&Ks[(8 * nt + ln4) * 80 + ub];
                    unsigned b0[2] = {FU(fK.x), FU(fK.y)};
                    unsigned b1[2] = {FU(fK.z), FU(fK.w)};
                    mma_tf32(s_acc[nt], a0, b0);
                    mma_tf32(s_acc[nt], a1, b1);
                }
            }

            // ---- scale + causal mask ----
            if (jt == mt) {
#pragma unroll
                for (int nt = 0; nt < 8; nt++)
#pragma unroll
                    for (int v = 0; v < 4; v++) {
                        int row = rowA + ((v >= 2) ? 8 : 0);
                        int col = 8 * nt + 2 * qd + (v & 1);
                        s_acc[nt][v] = (col > row) ? -1e30f : s_acc[nt][v] * scale;
                    }
            } else {
#pragma unroll
                for (int nt = 0; nt < 8; nt++)
#pragma unroll
                    for (int v = 0; v < 4; v++) s_acc[nt][v] *= scale;
            }

            // ---- online softmax ----
#pragma unroll
            for (int rr = 0; rr < 2; rr++) {
                float mx = -1e30f;
#pragma unroll
                for (int nt = 0; nt < 8; nt++)
                    mx = fmaxf(mx, fmaxf(s_acc[nt][2 * rr], s_acc[nt][2 * rr + 1]));
                mx = fmaxf(mx, __shfl_xor_sync(0xffffffffu, mx, 1));
                mx = fmaxf(mx, __shfl_xor_sync(0xffffffffu, mx, 2));
                float mnew  = fmaxf(m_run[rr], mx);
                float alpha = __expf(m_run[rr] - mnew);
                float rs = 0.f;
#pragma unroll
                for (int nt = 0; nt < 8; nt++) {
                    float p0 = __expf(s_acc[nt][2 * rr]     - mnew);
                    float p1 = __expf(s_acc[nt][2 * rr + 1] - mnew);
                    rs += p0 + p1;
                    s_acc[nt][2 * rr]     = p0;
                    s_acc[nt][2 * rr + 1] = p1;
                }
                rs += __shfl_xor_sync(0xffffffffu, rs, 1);
                rs += __shfl_xor_sync(0xffffffffu, rs, 2);
                l_run[rr] = l_run[rr] * alpha + rs;
                m_run[rr] = mnew;
#pragma unroll
                for (int nt = 0; nt < 8; nt++) {
                    o_acc[nt][2 * rr]     *= alpha;
                    o_acc[nt][2 * rr + 1] *= alpha;
                }
            }

            // ---- stash P (tf32) ----
#pragma unroll
            for (int nt = 0; nt < 8; nt++) {
                float2 p0 = {rne(s_acc[nt][0]), rne(s_acc[nt][1])};
                float2 p1 = {rne(s_acc[nt][2]), rne(s_acc[nt][3])};
                *(float2*)&Ps[rowA * 80 + 8 * nt + 2 * qd]       = p0;
                *(float2*)&Ps[(rowA + 8) * 80 + 8 * nt + 2 * qd] = p1;
            }
            __syncwarp();

            // ---- GEMM2: O += P V ----
#pragma unroll
            for (int jj = 0; jj < 4; jj++) {
                int ub = (qd + 4 * jj) * 4;
                float4 fA0 = *(float4*)&Ps[rowA * 80 + ub];
                float4 fA1 = *(float4*)&Ps[(rowA + 8) * 80 + ub];
                unsigned a0[4] = {FU(fA0.x), FU(fA1.x), FU(fA0.y), FU(fA1.y)};
                unsigned a1[4] = {FU(fA0.z), FU(fA1.z), FU(fA0.w), FU(fA1.w)};
#pragma unroll
                for (int nt = 0; nt < 8; nt++) {
                    int c = 8 * nt + ln4;
                    unsigned b0[2] = {FU(Vs[(ub + 0) * 70 + c]), FU(Vs[(ub + 1) * 70 + c])};
                    unsigned b1[2] = {FU(Vs[(ub + 2) * 70 + c]), FU(Vs[(ub + 3) * 70 + c])};
                    mma_tf32(o_acc[nt], a0, b0);
                    mma_tf32(o_acc[nt], a1, b1);
                }
            }
        }

        // ---- epilogue ----
        float inv0 = 1.f / l_run[0];
        float inv1 = 1.f / l_run[1];
        float* Og = g_O + ((size_t)b * SS + q0) * HH;
#pragma unroll
        for (int nt = 0; nt < 8; nt++) {
            float2 o0 = {o_acc[nt][0] * inv0, o_acc[nt][1] * inv0};
            float2 o1 = {o_acc[nt][2] * inv1, o_acc[nt][3] * inv1};
            *(float2*)&Og[rowA * HH + 8 * nt + 2 * qd]       = o0;
            *(float2*)&Og[(rowA + 8) * HH + 8 * nt + 2 * qd] = o1;
        }
    }
}

// ============================================================================
// Kernel 3: output projection, tf32 mma.  out[16384,512] = O @ Wo + bo.
// M-tile 128, N-tile 64, K=64 single chunk.  Same layouts as qkv.
// ============================================================================
__global__ __launch_bounds__(128) void outproj_tf32_kernel(
    const float* __restrict__ Wo, const float* __restrict__ bo,
    float* __restrict__ out)
{
    extern __shared__ float sm[];
    float* Os = sm;              // 128 x 80
    float* Ws = sm + 128 * 80;   // 64 x 70

    const int row0 = blockIdx.x * 128, n0 = blockIdx.y * 64;
    const int t = threadIdx.x, w = t >> 5, lane = t & 31;
    const int qd = lane & 3, ln4 = lane >> 2;
    const int rowA = 32 * w + ln4;

#pragma unroll
    for (int l = 0; l < 16; l++) {           // O tile 128 x 64
        int u = t + l * 128;
        int r = u >> 4, c4 = u & 15;
        float4 v = *(const float4*)(g_O + (size_t)(row0 + r) * HH + c4 * 4);
        v.x = rne(v.x); v.y = rne(v.y); v.z = rne(v.z); v.w = rne(v.w);
        *(float4*)&Os[r * 80 + c4 * 4] = v;
    }
#pragma unroll
    for (int l = 0; l < 8; l++) {            // Wo tile 64 x 64
        int u = t + l * 128;
        int kk = u >> 4, c4 = u & 15;
        float4 v = *(const float4*)(Wo + (size_t)kk * DD + n0 + c4 * 4);
        float2 lo = {rne(v.x), rne(v.y)}, hi = {rne(v.z), rne(v.w)};
        *(float2*)&Ws[kk * 70 + c4 * 4]     = lo;
        *(float2*)&Ws[kk * 70 + c4 * 4 + 2] = hi;
    }
    __syncthreads();

    float acc[2][8][4];
#pragma unroll
    for (int mf = 0; mf < 2; mf++)
#pragma unroll
        for (int nt = 0; nt < 8; nt++)
#pragma unroll
            for (int v = 0; v < 4; v++) acc[mf][nt][v] = 0.f;

#pragma unroll
    for (int jj = 0; jj < 4; jj++) {
        int ub = (qd + 4 * jj) * 4;
        float4 f0 = *(float4*)&Os[rowA * 80 + ub];
        float4 f1 = *(float4*)&Os[(rowA + 8) * 80 + ub];
        float4 f2 = *(float4*)&Os[(rowA + 16) * 80 + ub];
        float4 f3 = *(float4*)&Os[(rowA + 24) * 80 + ub];
        unsigned a00[4] = {FU(f0.x), FU(f1.x), FU(f0.y), FU(f1.y)};
        unsigned a01[4] = {FU(f0.z), FU(f1.z), FU(f0.w), FU(f1.w)};
        unsigned a10[4] = {FU(f2.x), FU(f3.x), FU(f2.y), FU(f3.y)};
        unsigned a11[4] = {FU(f2.z), FU(f3.z), FU(f2.w), FU(f3.w)};
#pragma unroll
        for (int nt = 0; nt < 8; nt++) {
            int c = 8 * nt + ln4;
            unsigned b0[2] = {FU(Ws[(ub + 0) * 70 + c]), FU(Ws[(ub + 1) * 70 + c])};
            unsigned b1[2] = {FU(Ws[(ub + 2) * 70 + c]), FU(Ws[(ub + 3) * 70 + c])};
            mma_tf32(acc[0][nt], a00, b0);
            mma_tf32(acc[0][nt], a01, b1);
            mma_tf32(acc[1][nt], a10, b0);
            mma_tf32(acc[1][nt], a11, b1);
        }
    }

#pragma unroll
    for (int mf = 0; mf < 2; mf++)
#pragma unroll
        for (int nt = 0; nt < 8; nt++) {
            int c = 8 * nt + 2 * qd;
            int row = row0 + rowA + 16 * mf;
            float b0 = bo[n0 + c], b1 = bo[n0 + c + 1];
            float2 v0 = {acc[mf][nt][0] + b0, acc[mf][nt][1] + b1};
            float2 v1 = {acc[mf][nt][2] + b0, acc[mf][nt][3] + b1};
            *(float2*)(out + (size_t)row * DD + n0 + c)       = v0;
            *(float2*)(out + (size_t)(row + 8) * DD + n0 + c) = v1;
        }
}

// ============================================================================
extern "C" void kernel_launch(void* const* d_in, const int* in_sizes, int n_in,
                              void* d_out, int out_size)
{
    const float* x  = (const float*)d_in[0];
    const float* Wq = (const float*)d_in[1];
    const float* bq = (const float*)d_in[2];
    const float* Wk = (const float*)d_in[3];
    const float* bk = (const float*)d_in[4];
    const float* Wv = (const float*)d_in[5];
    const float* bv = (const float*)d_in[6];
    const float* Wo = (const float*)d_in[7];
    const float* bo = (const float*)d_in[8];
    float* out = (float*)d_out;

    const int qkv_smem   = (128 * 80 + 64 * 70) * 4;              // 58880
    const int flash_smem = (3 * 64 * 80 + 64 * 70) * 4;           // 79360
    const int oprj_smem  = (128 * 80 + 64 * 70) * 4;              // 58880

    static int attr_set = 0;
    if (!attr_set) {
        cudaFuncSetAttribute(qkv_tf32_kernel,
                             cudaFuncAttributeMaxDynamicSharedMemorySize, qkv_smem);
        cudaFuncSetAttribute(flash_tf32_kernel,
                             cudaFuncAttributeMaxDynamicSharedMemorySize, flash_smem);
        cudaFuncSetAttribute(outproj_tf32_kernel,
                             cudaFuncAttributeMaxDynamicSharedMemorySize, oprj_smem);
        attr_set = 1;
    }

    qkv_tf32_kernel<<<dim3(NROW / 128, 3), 128, qkv_smem>>>(x, Wq, bq, Wk, bk, Wv, bv);
    flash_tf32_kernel<<<296, 128, flash_smem>>>();
    outproj_tf32_kernel<<<dim3(NROW / 128, DD / 64), 128, oprj_smem>>>(Wo, bo, out);
}

// round 8
// speedup vs baseline: 2.6918x; 1.3945x over previous
#include <cuda_runtime.h>

#define BB 4
#define SS 4096
#define DD 512
#define HH 64
#define NROW (BB * SS)   // 16384

__device__ float g_Q[NROW * HH];
__device__ float g_K[NROW * HH];
__device__ float g_V[NROW * HH];
__device__ float g_O[NROW * HH];
__device__ float g_Opart[2 * NROW * HH];   // unnormalized partial O
__device__ float g_ML[2 * NROW * 2];       // (m, l) per part per row
__device__ unsigned g_ctr;

__device__ __forceinline__ unsigned f2tf32(float f) {
    unsigned u;
    asm("cvt.rna.tf32.f32 %0, %1;" : "=r"(u) : "f"(f));
    return u;
}
__device__ __forceinline__ float rne(float f) { return __uint_as_float(f2tf32(f)); }

__device__ __forceinline__ void mma_tf32(float (&d)[4], const unsigned (&a)[4],
                                         const unsigned (&b)[2]) {
    asm volatile(
        "mma.sync.aligned.m16n8k8.row.col.f32.tf32.tf32.f32 "
        "{%0,%1,%2,%3}, {%4,%5,%6,%7}, {%8,%9}, {%0,%1,%2,%3};"
        : "+f"(d[0]), "+f"(d[1]), "+f"(d[2]), "+f"(d[3])
        : "r"(a[0]), "r"(a[1]), "r"(a[2]), "r"(a[3]), "r"(b[0]), "r"(b[1]));
}
#define FU __float_as_uint

// ============================================================================
// Kernel 1: QKV projections, tf32 mma.  256 thr / 8 warps, M-tile 128.
// Warp w owns rows [16w,16w+16) x all 64 cols -> acc[8][4] (32 regs).
// Xs [128][80] conflict-free LDS.128 A frags; Ws [64][70] conflict-free scalar B.
// ============================================================================
__global__ __launch_bounds__(256) void qkv_tf32_kernel(
    const float* __restrict__ x,
    const float* __restrict__ Wq, const float* __restrict__ bq,
    const float* __restrict__ Wk, const float* __restrict__ bk,
    const float* __restrict__ Wv, const float* __restrict__ bv)
{
    extern __shared__ float sm[];
    float* Xs = sm;              // 128 x 80
    float* Ws = sm + 128 * 80;   // 64 x 70

    const float* W; const float* bias; float* out;
    int which = blockIdx.y;
    if (which == 0)      { W = Wq; bias = bq; out = g_Q; }
    else if (which == 1) { W = Wk; bias = bk; out = g_K; }
    else                 { W = Wv; bias = bv; out = g_V; }

    if (blockIdx.x == 0 && which == 0 && threadIdx.x == 0) g_ctr = 0u;

    const int row0 = blockIdx.x * 128;
    const int t = threadIdx.x, w = t >> 5, lane = t & 31;
    const int qd = lane & 3, ln4 = lane >> 2;
    const int rowA = 16 * w + ln4;

    float acc[8][4];
#pragma unroll
    for (int nt = 0; nt < 8; nt++)
#pragma unroll
        for (int v = 0; v < 4; v++) acc[nt][v] = 0.f;

    for (int k0 = 0; k0 < DD; k0 += 64) {
        __syncthreads();
#pragma unroll
        for (int l = 0; l < 8; l++) {            // x tile 128 x 64
            int u = t + l * 256;
            int r = u >> 4, c4 = u & 15;
            float4 v = *(const float4*)(x + (size_t)(row0 + r) * DD + k0 + c4 * 4);
            v.x = rne(v.x); v.y = rne(v.y); v.z = rne(v.z); v.w = rne(v.w);
            *(float4*)&Xs[r * 80 + c4 * 4] = v;
        }
#pragma unroll
        for (int l = 0; l < 4; l++) {            // W tile 64 x 64
            int u = t + l * 256;
            int kk = u >> 4, c4 = u & 15;
            float4 v = *(const float4*)(W + (size_t)(k0 + kk) * HH + c4 * 4);
            float2 lo = {rne(v.x), rne(v.y)}, hi = {rne(v.z), rne(v.w)};
            *(float2*)&Ws[kk * 70 + c4 * 4]     = lo;
            *(float2*)&Ws[kk * 70 + c4 * 4 + 2] = hi;
        }
        __syncthreads();

#pragma unroll
        for (int jj = 0; jj < 4; jj++) {
            int ub = (qd + 4 * jj) * 4;
            float4 f0 = *(float4*)&Xs[rowA * 80 + ub];
            float4 f1 = *(float4*)&Xs[(rowA + 8) * 80 + ub];
            unsigned a0[4] = {FU(f0.x), FU(f1.x), FU(f0.y), FU(f1.y)};
            unsigned a1[4] = {FU(f0.z), FU(f1.z), FU(f0.w), FU(f1.w)};
#pragma unroll
            for (int nt = 0; nt < 8; nt++) {
                int c = 8 * nt + ln4;
                unsigned b0[2] = {FU(Ws[(ub + 0) * 70 + c]), FU(Ws[(ub + 1) * 70 + c])};
                unsigned b1[2] = {FU(Ws[(ub + 2) * 70 + c]), FU(Ws[(ub + 3) * 70 + c])};
                mma_tf32(acc[nt], a0, b0);
                mma_tf32(acc[nt], a1, b1);
            }
        }
    }

#pragma unroll
    for (int nt = 0; nt < 8; nt++) {
        int c = 8 * nt + 2 * qd;
        int row = row0 + rowA;
        float b0 = bias[c], b1 = bias[c + 1];
        float2 v0 = {acc[nt][0] + b0, acc[nt][1] + b1};
        float2 v1 = {acc[nt][2] + b0, acc[nt][3] + b1};
        *(float2*)(out + (size_t)row * HH + c)       = v0;
        *(float2*)(out + (size_t)(row + 8) * HH + c) = v1;
    }
}

// ============================================================================
// Kernel 2: causal flash attention, tf32 mma, split-KV persistent queue.
// 448 jobs: tiles mt>=16 split into two j-ranges (each <=33 units), dispensed
// big-first.  Split jobs write unnormalized O + (m,l); combine merges.
// ============================================================================
__global__ __launch_bounds__(128) void flash_tf32_kernel()
{
    extern __shared__ float sm[];
    float* Qs = sm;                   // 64 x 80
    float* Ks = sm + 64 * 80;         // 64 x 80
    float* Ps = sm + 2 * 64 * 80;     // 64 x 80
    float* Vs = sm + 3 * 64 * 80;     // 64 x 70
    __shared__ unsigned s_tile;

    const int t = threadIdx.x, w = t >> 5, lane = t & 31;
    const int qd = lane & 3, ln4 = lane >> 2;
    const int rowA = 16 * w + ln4;
    const float scale = 0.015625f;    // 1/sqrt(4096)

    while (true) {
        if (t == 0) s_tile = atomicAdd(&g_ctr, 1u);
        __syncthreads();
        unsigned i = s_tile;
        if (i >= 448u) break;

        int mt, b, half, jlo, jhi, split;
        if (i < 384u) {                       // split jobs, mt 63..16
            mt = 63 - (int)(i >> 3);
            b  = (int)((i >> 1) & 3u);
            half = (int)(i & 1u);
            split = 1;
            int mid = (mt + 1) >> 1;
            jlo = half ? mid : 0;
            jhi = half ? mt  : mid - 1;
        } else {                              // unsplit, mt 15..0
            unsigned u = i - 384u;
            mt = 15 - (int)(u >> 2);
            b  = (int)(u & 3u);
            half = 0; split = 0; jlo = 0; jhi = mt;
        }
        const int q0 = mt * 64;

        const float* Qg = g_Q + ((size_t)b * SS + q0) * HH;
#pragma unroll
        for (int l = 0; l < 8; l++) {
            int u = t + l * 128;
            int r = u >> 4, c4 = u & 15;
            *(float4*)&Qs[r * 80 + c4 * 4] = *(const float4*)(Qg + r * HH + c4 * 4);
        }

        float o_acc[8][4];
        float m_run[2] = {-1e30f, -1e30f};
        float l_run[2] = {0.f, 0.f};
#pragma unroll
        for (int nt = 0; nt < 8; nt++)
#pragma unroll
            for (int v = 0; v < 4; v++) o_acc[nt][v] = 0.f;

        for (int jt = jlo; jt <= jhi; jt++) {
            __syncthreads();
            {
                const float* Kg = g_K + ((size_t)b * SS + jt * 64) * HH;
                const float* Vg = g_V + ((size_t)b * SS + jt * 64) * HH;
#pragma unroll
                for (int l = 0; l < 8; l++) {
                    int u = t + l * 128;
                    int r = u >> 4, c4 = u & 15;
                    *(float4*)&Ks[r * 80 + c4 * 4] =
                        *(const float4*)(Kg + r * HH + c4 * 4);
                    float4 vv = *(const float4*)(Vg + r * HH + c4 * 4);
                    float2 lo = {rne(vv.x), rne(vv.y)}, hi = {rne(vv.z), rne(vv.w)};
                    *(float2*)&Vs[r * 70 + c4 * 4]     = lo;
                    *(float2*)&Vs[r * 70 + c4 * 4 + 2] = hi;
                }
            }
            __syncthreads();

            // ---- GEMM1: S = Q K^T ----
            float s_acc[8][4];
#pragma unroll
            for (int nt = 0; nt < 8; nt++)
#pragma unroll
                for (int v = 0; v < 4; v++) s_acc[nt][v] = 0.f;

#pragma unroll
            for (int jj = 0; jj < 4; jj++) {
                int ub = (qd + 4 * jj) * 4;
                float4 fA = *(float4*)&Qs[rowA * 80 + ub];
                float4 fB = *(float4*)&Qs[(rowA + 8) * 80 + ub];
                unsigned a0[4] = {FU(fA.x), FU(fB.x), FU(fA.y), FU(fB.y)};
                unsigned a1[4] = {FU(fA.z), FU(fB.z), FU(fA.w), FU(fB.w)};
#pragma unroll
                for (int nt = 0; nt < 8; nt++) {
                    float4 fK = *(float4*)&Ks[(8 * nt + ln4) * 80 + ub];
                    unsigned b0[2] = {FU(fK.x), FU(fK.y)};
                    unsigned b1[2] = {FU(fK.z), FU(fK.w)};
                    mma_tf32(s_acc[nt], a0, b0);
                    mma_tf32(s_acc[nt], a1, b1);
                }
            }

            // ---- scale + causal mask (diagonal tile only) ----
            if (jt == mt) {
#pragma unroll
                for (int nt = 0; nt < 8; nt++)
#pragma unroll
                    for (int v = 0; v < 4; v++) {
                        int row = rowA + ((v >= 2) ? 8 : 0);
                        int col = 8 * nt + 2 * qd + (v & 1);
                        s_acc[nt][v] = (col > row) ? -1e30f : s_acc[nt][v] * scale;
                    }
            } else {
#pragma unroll
                for (int nt = 0; nt < 8; nt++)
#pragma unroll
                    for (int v = 0; v < 4; v++) s_acc[nt][v] *= scale;
            }

            // ---- online softmax ----
#pragma unroll
            for (int rr = 0; rr < 2; rr++) {
                float mx = -1e30f;
#pragma unroll
                for (int nt = 0; nt < 8; nt++)
                    mx = fmaxf(mx, fmaxf(s_acc[nt][2 * rr], s_acc[nt][2 * rr + 1]));
                mx = fmaxf(mx, __shfl_xor_sync(0xffffffffu, mx, 1));
                mx = fmaxf(mx, __shfl_xor_sync(0xffffffffu, mx, 2));
                float mnew  = fmaxf(m_run[rr], mx);
                float alpha = __expf(m_run[rr] - mnew);
                float rs = 0.f;
#pragma unroll
                for (int nt = 0; nt < 8; nt++) {
                    float p0 = __expf(s_acc[nt][2 * rr]     - mnew);
                    float p1 = __expf(s_acc[nt][2 * rr + 1] - mnew);
                    rs += p0 + p1;
                    s_acc[nt][2 * rr]     = p0;
                    s_acc[nt][2 * rr + 1] = p1;
                }
                rs += __shfl_xor_sync(0xffffffffu, rs, 1);
                rs += __shfl_xor_sync(0xffffffffu, rs, 2);
                l_run[rr] = l_run[rr] * alpha + rs;
                m_run[rr] = mnew;
#pragma unroll
                for (int nt = 0; nt < 8; nt++) {
                    o_acc[nt][2 * rr]     *= alpha;
                    o_acc[nt][2 * rr + 1] *= alpha;
                }
            }

            // ---- stash P (tf32) ----
#pragma unroll
            for (int nt = 0; nt < 8; nt++) {
                float2 p0 = {rne(s_acc[nt][0]), rne(s_acc[nt][1])};
                float2 p1 = {rne(s_acc[nt][2]), rne(s_acc[nt][3])};
                *(float2*)&Ps[rowA * 80 + 8 * nt + 2 * qd]       = p0;
                *(float2*)&Ps[(rowA + 8) * 80 + 8 * nt + 2 * qd] = p1;
            }
            __syncwarp();

            // ---- GEMM2: O += P V ----
#pragma unroll
            for (int jj = 0; jj < 4; jj++) {
                int ub = (qd + 4 * jj) * 4;
                float4 fA0 = *(float4*)&Ps[rowA * 80 + ub];
                float4 fA1 = *(float4*)&Ps[(rowA + 8) * 80 + ub];
                unsigned a0[4] = {FU(fA0.x), FU(fA1.x), FU(fA0.y), FU(fA1.y)};
                unsigned a1[4] = {FU(fA0.z), FU(fA1.z), FU(fA0.w), FU(fA1.w)};
#pragma unroll
                for (int nt = 0; nt < 8; nt++) {
                    int c = 8 * nt + ln4;
                    unsigned b0[2] = {FU(Vs[(ub + 0) * 70 + c]), FU(Vs[(ub + 1) * 70 + c])};
                    unsigned b1[2] = {FU(Vs[(ub + 2) * 70 + c]), FU(Vs[(ub + 3) * 70 + c])};
                    mma_tf32(o_acc[nt], a0, b0);
                    mma_tf32(o_acc[nt], a1, b1);
                }
            }
        }

        // ---- epilogue ----
        if (!split) {
            float inv0 = 1.f / l_run[0];
            float inv1 = 1.f / l_run[1];
            float* Og = g_O + ((size_t)b * SS + q0) * HH;
#pragma unroll
            for (int nt = 0; nt < 8; nt++) {
                float2 o0 = {o_acc[nt][0] * inv0, o_acc[nt][1] * inv0};
                float2 o1 = {o_acc[nt][2] * inv1, o_acc[nt][3] * inv1};
                *(float2*)&Og[rowA * HH + 8 * nt + 2 * qd]       = o0;
                *(float2*)&Og[(rowA + 8) * HH + 8 * nt + 2 * qd] = o1;
            }
        } else {
            size_t rbase = (size_t)b * SS + q0;
            float* Op = g_Opart + (size_t)half * NROW * HH + rbase * HH;
#pragma unroll
            for (int nt = 0; nt < 8; nt++) {
                float2 o0 = {o_acc[nt][0], o_acc[nt][1]};
                float2 o1 = {o_acc[nt][2], o_acc[nt][3]};
                *(float2*)&Op[rowA * HH + 8 * nt + 2 * qd]       = o0;
                *(float2*)&Op[(rowA + 8) * HH + 8 * nt + 2 * qd] = o1;
            }
            if (qd == 0) {   // (m,l) replicated across quad by the shuffles
                float* ML = g_ML + ((size_t)half * NROW + rbase) * 2;
                *(float2*)&ML[rowA * 2]       = make_float2(m_run[0], l_run[0]);
                *(float2*)&ML[(rowA + 8) * 2] = make_float2(m_run[1], l_run[1]);
            }
        }
    }
}

// ============================================================================
// Kernel 2b: merge the two split-KV halves (rows with mt >= 16 only).
// Exact softmax merge: m=max, O=(O0 e^{m0-m} + O1 e^{m1-m}) / (l0 e^.. + l1 e..)
// ============================================================================
__global__ __launch_bounds__(128) void combine_kernel()
{
    int rid = blockIdx.x * 2 + (threadIdx.x >> 6);   // 2 rows per block
    int c = threadIdx.x & 63;
    int batch = rid / 3072;
    int r_in  = (rid % 3072) + 1024;                 // rows with mt>=16
    size_t row = (size_t)batch * SS + r_in;

    float2 ml0 = *(float2*)&g_ML[row * 2];
    float2 ml1 = *(float2*)&g_ML[(NROW + row) * 2];
    float mn = fmaxf(ml0.x, ml1.x);
    float a0 = __expf(ml0.x - mn), a1 = __expf(ml1.x - mn);
    float inv = 1.f / (ml0.y * a0 + ml1.y * a1);
    float o0 = g_Opart[row * HH + c];
    float o1 = g_Opart[(size_t)NROW * HH + row * HH + c];
    g_O[row * HH + c] = (o0 * a0 + o1 * a1) * inv;
}

// ============================================================================
// Kernel 3: output projection, tf32 mma.  256 thr / 8 warps, M 128, N 64, K 64.
// ============================================================================
__global__ __launch_bounds__(256) void outproj_tf32_kernel(
    const float* __restrict__ Wo, const float* __restrict__ bo,
    float* __restrict__ out)
{
    extern __shared__ float sm[];
    float* Os = sm;              // 128 x 80
    float* Ws = sm + 128 * 80;   // 64 x 70

    const int row0 = blockIdx.x * 128, n0 = blockIdx.y * 64;
    const int t = threadIdx.x, w = t >> 5, lane = t & 31;
    const int qd = lane & 3, ln4 = lane >> 2;
    const int rowA = 16 * w + ln4;

#pragma unroll
    for (int l = 0; l < 8; l++) {            // O tile 128 x 64
        int u = t + l * 256;
        int r = u >> 4, c4 = u & 15;
        float4 v = *(const float4*)(g_O + (size_t)(row0 + r) * HH + c4 * 4);
        v.x = rne(v.x); v.y = rne(v.y); v.z = rne(v.z); v.w = rne(v.w);
        *(float4*)&Os[r * 80 + c4 * 4] = v;
    }
#pragma unroll
    for (int l = 0; l < 4; l++) {            // Wo tile 64 x 64
        int u = t + l * 256;
        int kk = u >> 4, c4 = u & 15;
        float4 v = *(const float4*)(Wo + (size_t)kk * DD + n0 + c4 * 4);
        float2 lo = {rne(v.x), rne(v.y)}, hi = {rne(v.z), rne(v.w)};
        *(float2*)&Ws[kk * 70 + c4 * 4]     = lo;
        *(float2*)&Ws[kk * 70 + c4 * 4 + 2] = hi;
    }
    __syncthreads();

    float acc[8][4];
#pragma unroll
    for (int nt = 0; nt < 8; nt++)
#pragma unroll
        for (int v = 0; v < 4; v++) acc[nt][v] = 0.f;

#pragma unroll
    for (int jj = 0; jj < 4; jj++) {
        int ub = (qd + 4 * jj) * 4;
        float4 f0 = *(float4*)&Os[rowA * 80 + ub];
        float4 f1 = *(float4*)&Os[(rowA + 8) * 80 + ub];
        unsigned a0[4] = {FU(f0.x), FU(f1.x), FU(f0.y), FU(f1.y)};
        unsigned a1[4] = {FU(f0.z), FU(f1.z), FU(f0.w), FU(f1.w)};
#pragma unroll
        for (int nt = 0; nt < 8; nt++) {
            int c = 8 * nt + ln4;
            unsigned b0[2] = {FU(Ws[(ub + 0) * 70 + c]), FU(Ws[(ub + 1) * 70 + c])};
            unsigned b1[2] = {FU(Ws[(ub + 2) * 70 + c]), FU(Ws[(ub + 3) * 70 + c])};
            mma_tf32(acc[nt], a0, b0);
            mma_tf32(acc[nt], a1, b1);
        }
    }

#pragma unroll
    for (int nt = 0; nt < 8; nt++) {
        int c = 8 * nt + 2 * qd;
        int row = row0 + rowA;
        float b0 = bo[n0 + c], b1 = bo[n0 + c + 1];
        float2 v0 = {acc[nt][0] + b0, acc[nt][1] + b1};
        float2 v1 = {acc[nt][2] + b0, acc[nt][3] + b1};
        *(float2*)(out + (size_t)row * DD + n0 + c)       = v0;
        *(float2*)(out + (size_t)(row + 8) * DD + n0 + c) = v1;
    }
}

// ============================================================================
extern "C" void kernel_launch(void* const* d_in, const int* in_sizes, int n_in,
                              void* d_out, int out_size)
{
    const float* x  = (const float*)d_in[0];
    const float* Wq = (const float*)d_in[1];
    const float* bq = (const float*)d_in[2];
    const float* Wk = (const float*)d_in[3];
    const float* bk = (const float*)d_in[4];
    const float* Wv = (const float*)d_in[5];
    const float* bv = (const float*)d_in[6];
    const float* Wo = (const float*)d_in[7];
    const float* bo = (const float*)d_in[8];
    float* out = (float*)d_out;

    const int proj_smem  = (128 * 80 + 64 * 70) * 4;     // 58880
    const int flash_smem = (3 * 64 * 80 + 64 * 70) * 4;  // 79360

    static int attr_set = 0;
    if (!attr_set) {
        cudaFuncSetAttribute(qkv_tf32_kernel,
                             cudaFuncAttributeMaxDynamicSharedMemorySize, proj_smem);
        cudaFuncSetAttribute(flash_tf32_kernel,
                             cudaFuncAttributeMaxDynamicSharedMemorySize, flash_smem);
        cudaFuncSetAttribute(outproj_tf32_kernel,
                             cudaFuncAttributeMaxDynamicSharedMemorySize, proj_smem);
        attr_set = 1;
    }

    qkv_tf32_kernel<<<dim3(NROW / 128, 3), 256, proj_smem>>>(x, Wq, bq, Wk, bk, Wv, bv);
    flash_tf32_kernel<<<296, 128, flash_smem>>>();
    combine_kernel<<<(BB * 3072) / 2, 128>>>();
    outproj_tf32_kernel<<<dim3(NROW / 128, DD / 64), 256, proj_smem>>>(Wo, bo, out);
}

// round 10
// speedup vs baseline: 2.9123x; 1.0819x over previous
#include <cuda_runtime.h>

#define BB 4
#define SS 4096
#define DD 512
#define HH 64
#define NROW (BB * SS)   // 16384

__device__ float g_Q[NROW * HH];
__device__ float g_K[NROW * HH];
__device__ float g_V[NROW * HH];
__device__ float g_O[NROW * HH];
__device__ float g_Opart[4 * NROW * HH];   // unnormalized partial O (4 slots)
__device__ float g_ML[4 * NROW * 2];       // (m, l) per slot per row
__device__ unsigned g_ctr;

__device__ __forceinline__ unsigned f2tf32(float f) {
    unsigned u;
    asm("cvt.rna.tf32.f32 %0, %1;" : "=r"(u) : "f"(f));
    return u;
}
__device__ __forceinline__ float rne(float f) { return __uint_as_float(f2tf32(f)); }

__device__ __forceinline__ void mma_tf32(float (&d)[4], const unsigned (&a)[4],
                                         const unsigned (&b)[2]) {
    asm volatile(
        "mma.sync.aligned.m16n8k8.row.col.f32.tf32.tf32.f32 "
        "{%0,%1,%2,%3}, {%4,%5,%6,%7}, {%8,%9}, {%0,%1,%2,%3};"
        : "+f"(d[0]), "+f"(d[1]), "+f"(d[2]), "+f"(d[3])
        : "r"(a[0]), "r"(a[1]), "r"(a[2]), "r"(a[3]), "r"(b[0]), "r"(b[1]));
}
#define FU __float_as_uint

// ============================================================================
// Kernel 1: QKV projections, tf32 mma, register-prefetch over K chunks.
// 256 thr / 8 warps, M-tile 128.  Xs [128][80], Ws [64][70] (conflict-free).
// ============================================================================
__global__ __launch_bounds__(256) void qkv_tf32_kernel(
    const float* __restrict__ x,
    const float* __restrict__ Wq, const float* __restrict__ bq,
    const float* __restrict__ Wk, const float* __restrict__ bk,
    const float* __restrict__ Wv, const float* __restrict__ bv)
{
    extern __shared__ float sm[];
    float* Xs = sm;              // 128 x 80
    float* Ws = sm + 128 * 80;   // 64 x 70

    const float* W; const float* bias; float* out;
    int which = blockIdx.y;
    if (which == 0)      { W = Wq; bias = bq; out = g_Q; }
    else if (which == 1) { W = Wk; bias = bk; out = g_K; }
    else                 { W = Wv; bias = bv; out = g_V; }

    if (blockIdx.x == 0 && which == 0 && threadIdx.x == 0) g_ctr = 0u;

    const int row0 = blockIdx.x * 128;
    const int t = threadIdx.x, w = t >> 5, lane = t & 31;
    const int qd = lane & 3, ln4 = lane >> 2;
    const int rowA = 16 * w + ln4;

    float acc[8][4];
#pragma unroll
    for (int nt = 0; nt < 8; nt++)
#pragma unroll
        for (int v = 0; v < 4; v++) acc[nt][v] = 0.f;

    float4 xr[8], wr[4];
#pragma unroll
    for (int l = 0; l < 8; l++) {
        int u = t + l * 256, r = u >> 4, c4 = u & 15;
        xr[l] = *(const float4*)(x + (size_t)(row0 + r) * DD + c4 * 4);
    }
#pragma unroll
    for (int l = 0; l < 4; l++) {
        int u = t + l * 256, kk = u >> 4, c4 = u & 15;
        wr[l] = *(const float4*)(W + (size_t)kk * HH + c4 * 4);
    }

    for (int k0 = 0; k0 < DD; k0 += 64) {
        __syncthreads();
#pragma unroll
        for (int l = 0; l < 8; l++) {
            int u = t + l * 256, r = u >> 4, c4 = u & 15;
            float4 v = xr[l];
            v.x = rne(v.x); v.y = rne(v.y); v.z = rne(v.z); v.w = rne(v.w);
            *(float4*)&Xs[r * 80 + c4 * 4] = v;
        }
#pragma unroll
        for (int l = 0; l < 4; l++) {
            int u = t + l * 256, kk = u >> 4, c4 = u & 15;
            float4 v = wr[l];
            float2 lo = {rne(v.x), rne(v.y)}, hi = {rne(v.z), rne(v.w)};
            *(float2*)&Ws[kk * 70 + c4 * 4]     = lo;
            *(float2*)&Ws[kk * 70 + c4 * 4 + 2] = hi;
        }
        __syncthreads();

        if (k0 + 64 < DD) {   // prefetch next chunk under the MMAs
#pragma unroll
            for (int l = 0; l < 8; l++) {
                int u = t + l * 256, r = u >> 4, c4 = u & 15;
                xr[l] = *(const float4*)(x + (size_t)(row0 + r) * DD + (k0 + 64) + c4 * 4);
            }
#pragma unroll
            for (int l = 0; l < 4; l++) {
                int u = t + l * 256, kk = u >> 4, c4 = u & 15;
                wr[l] = *(const float4*)(W + (size_t)(k0 + 64 + kk) * HH + c4 * 4);
            }
        }

#pragma unroll
        for (int jj = 0; jj < 4; jj++) {
            int ub = (qd + 4 * jj) * 4;
            float4 f0 = *(float4*)&Xs[rowA * 80 + ub];
            float4 f1 = *(float4*)&Xs[(rowA + 8) * 80 + ub];
            unsigned a0[4] = {FU(f0.x), FU(f1.x), FU(f0.y), FU(f1.y)};
            unsigned a1[4] = {FU(f0.z), FU(f1.z), FU(f0.w), FU(f1.w)};
#pragma unroll
            for (int nt = 0; nt < 8; nt++) {
                int c = 8 * nt + ln4;
                unsigned b0[2] = {FU(Ws[(ub + 0) * 70 + c]), FU(Ws[(ub + 1) * 70 + c])};
                unsigned b1[2] = {FU(Ws[(ub + 2) * 70 + c]), FU(Ws[(ub + 3) * 70 + c])};
                mma_tf32(acc[nt], a0, b0);
                mma_tf32(acc[nt], a1, b1);
            }
        }
    }

#pragma unroll
    for (int nt = 0; nt < 8; nt++) {
        int c = 8 * nt + 2 * qd;
        int row = row0 + rowA;
        float b0 = bias[c], b1 = bias[c + 1];
        float2 v0 = {acc[nt][0] + b0, acc[nt][1] + b1};
        float2 v1 = {acc[nt][2] + b0, acc[nt][3] + b1};
        *(float2*)(out + (size_t)row * HH + c)       = v0;
        *(float2*)(out + (size_t)(row + 8) * HH + c) = v1;
    }
}

// ============================================================================
// Kernel 2: causal flash attention, tf32 mma, fine split-KV + K/V prefetch.
// 704 jobs: mt>=32 -> 4 parts, 16<=mt<32 -> 2 parts, else unsplit.
// Max job 17 units vs 28-unit worker average -> balanced.
// ============================================================================
__global__ __launch_bounds__(128) void flash_tf32_kernel()
{
    extern __shared__ float sm[];
    float* Qs = sm;                   // 64 x 80
    float* Ks = sm + 64 * 80;         // 64 x 80
    float* Ps = sm + 2 * 64 * 80;     // 64 x 80
    float* Vs = sm + 3 * 64 * 80;     // 64 x 70
    __shared__ unsigned s_tile;

    const int t = threadIdx.x, w = t >> 5, lane = t & 31;
    const int qd = lane & 3, ln4 = lane >> 2;
    const int rowA = 16 * w + ln4;
    const float scale = 0.015625f;    // 1/sqrt(4096)

    while (true) {
        if (t == 0) s_tile = atomicAdd(&g_ctr, 1u);
        __syncthreads();
        unsigned i = s_tile;
        if (i >= 704u) break;

        int mt, b, part, jlo, jhi, split;
        if (i < 512u) {                       // mt 63..32, 4-way split
            mt = 63 - (int)(i >> 4);
            int sub = (int)(i & 15u);
            b = sub >> 2; part = sub & 3; split = 1;
            jlo = ((mt + 1) * part) >> 2;
            jhi = (((mt + 1) * (part + 1)) >> 2) - 1;
        } else if (i < 640u) {                // mt 31..16, 2-way split
            unsigned u = i - 512u;
            mt = 31 - (int)(u >> 3);
            int sub = (int)(u & 7u);
            b = sub >> 1; part = sub & 1; split = 1;
            jlo = ((mt + 1) * part) >> 1;
            jhi = (((mt + 1) * (part + 1)) >> 1) - 1;
        } else {                              // mt 15..0, unsplit
            unsigned u = i - 640u;
            mt = 15 - (int)(u >> 2);
            b = (int)(u & 3u);
            part = 0; split = 0; jlo = 0; jhi = mt;
        }
        const int q0 = mt * 64;

        const float* Qg = g_Q + ((size_t)b * SS + q0) * HH;
#pragma unroll
        for (int l = 0; l < 8; l++) {
            int u = t + l * 128, r = u >> 4, c4 = u & 15;
            *(float4*)&Qs[r * 80 + c4 * 4] = *(const float4*)(Qg + r * HH + c4 * 4);
        }

        // prologue prefetch of K/V tile jlo
        float4 kr[8], vr[8];
        {
            const float* Kg = g_K + ((size_t)b * SS + jlo * 64) * HH;
            const float* Vg = g_V + ((size_t)b * SS + jlo * 64) * HH;
#pragma unroll
            for (int l = 0; l < 8; l++) {
                int u = t + l * 128, r = u >> 4, c4 = u & 15;
                kr[l] = *(const float4*)(Kg + r * HH + c4 * 4);
                vr[l] = *(const float4*)(Vg + r * HH + c4 * 4);
            }
        }

        float o_acc[8][4];
        float m_run[2] = {-1e30f, -1e30f};
        float l_run[2] = {0.f, 0.f};
#pragma unroll
        for (int nt = 0; nt < 8; nt++)
#pragma unroll
            for (int v = 0; v < 4; v++) o_acc[nt][v] = 0.f;

        for (int jt = jlo; jt <= jhi; jt++) {
            __syncthreads();
#pragma unroll
            for (int l = 0; l < 8; l++) {
                int u = t + l * 128, r = u >> 4, c4 = u & 15;
                *(float4*)&Ks[r * 80 + c4 * 4] = kr[l];
                float4 vv = vr[l];
                float2 lo = {rne(vv.x), rne(vv.y)}, hi = {rne(vv.z), rne(vv.w)};
                *(float2*)&Vs[r * 70 + c4 * 4]     = lo;
                *(float2*)&Vs[r * 70 + c4 * 4 + 2] = hi;
            }
            __syncthreads();

            if (jt < jhi) {   // prefetch next K/V under the compute
                const float* Kg = g_K + ((size_t)b * SS + (jt + 1) * 64) * HH;
                const float* Vg = g_V + ((size_t)b * SS + (jt + 1) * 64) * HH;
#pragma unroll
                for (int l = 0; l < 8; l++) {
                    int u = t + l * 128, r = u >> 4, c4 = u & 15;
                    kr[l] = *(const float4*)(Kg + r * HH + c4 * 4);
                    vr[l] = *(const float4*)(Vg + r * HH + c4 * 4);
                }
            }

            // ---- GEMM1: S = Q K^T ----
            float s_acc[8][4];
#pragma unroll
            for (int nt = 0; nt < 8; nt++)
#pragma unroll
                for (int v = 0; v < 4; v++) s_acc[nt][v] = 0.f;

#pragma unroll
            for (int jj = 0; jj < 4; jj++) {
                int ub = (qd + 4 * jj) * 4;
                float4 fA = *(float4*)&Qs[rowA * 80 + ub];
                float4 fB = *(float4*)&Qs[(rowA + 8) * 80 + ub];
                unsigned a0[4] = {FU(fA.x), FU(fB.x), FU(fA.y), FU(fB.y)};
                unsigned a1[4] = {FU(fA.z), FU(fB.z), FU(fA.w), FU(fB.w)};
#pragma unroll
                for (int nt = 0; nt < 8; nt++) {
                    float4 fK = *(float4*)&Ks[(8 * nt + ln4) * 80 + ub];
                    unsigned b0[2] = {FU(fK.x), FU(fK.y)};
                    unsigned b1[2] = {FU(fK.z), FU(fK.w)};
                    mma_tf32(s_acc[nt], a0, b0);
                    mma_tf32(s_acc[nt], a1, b1);
                }
            }

            // ---- scale + causal mask (diagonal tile only) ----
            if (jt == mt) {
#pragma unroll
                for (int nt = 0; nt < 8; nt++)
#pragma unroll
                    for (int v = 0; v < 4; v++) {
                        int row = rowA + ((v >= 2) ? 8 : 0);
                        int col = 8 * nt + 2 * qd + (v & 1);
                        s_acc[nt][v] = (col > row) ? -1e30f : s_acc[nt][v] * scale;
                    }
            } else {
#pragma unroll
                for (int nt = 0; nt < 8; nt++)
#pragma unroll
                    for (int v = 0; v < 4; v++) s_acc[nt][v] *= scale;
            }

            // ---- online softmax ----
#pragma unroll
            for (int rr = 0; rr < 2; rr++) {
                float mx = -1e30f;
#pragma unroll
                for (int nt = 0; nt < 8; nt++)
                    mx = fmaxf(mx, fmaxf(s_acc[nt][2 * rr], s_acc[nt][2 * rr + 1]));
                mx = fmaxf(mx, __shfl_xor_sync(0xffffffffu, mx, 1));
                mx = fmaxf(mx, __shfl_xor_sync(0xffffffffu, mx, 2));
                float mnew  = fmaxf(m_run[rr], mx);
                float alpha = __expf(m_run[rr] - mnew);
                float rs = 0.f;
#pragma unroll
                for (int nt = 0; nt < 8; nt++) {
                    float p0 = __expf(s_acc[nt][2 * rr]     - mnew);
                    float p1 = __expf(s_acc[nt][2 * rr + 1] - mnew);
                    rs += p0 + p1;
                    s_acc[nt][2 * rr]     = p0;
                    s_acc[nt][2 * rr + 1] = p1;
                }
                rs += __shfl_xor_sync(0xffffffffu, rs, 1);
                rs += __shfl_xor_sync(0xffffffffu, rs, 2);
                l_run[rr] = l_run[rr] * alpha + rs;
                m_run[rr] = mnew;
#pragma unroll
                for (int nt = 0; nt < 8; nt++) {
                    o_acc[nt][2 * rr]     *= alpha;
                    o_acc[nt][2 * rr + 1] *= alpha;
                }
            }

            // ---- stash P (tf32); warp-private rows -> syncwarp only ----
#pragma unroll
            for (int nt = 0; nt < 8; nt++) {
                float2 p0 = {rne(s_acc[nt][0]), rne(s_acc[nt][1])};
                float2 p1 = {rne(s_acc[nt][2]), rne(s_acc[nt][3])};
                *(float2*)&Ps[rowA * 80 + 8 * nt + 2 * qd]       = p0;
                *(float2*)&Ps[(rowA + 8) * 80 + 8 * nt + 2 * qd] = p1;
            }
            __syncwarp();

            // ---- GEMM2: O += P V ----
#pragma unroll
            for (int jj = 0; jj < 4; jj++) {
                int ub = (qd + 4 * jj) * 4;
                float4 fA0 = *(float4*)&Ps[rowA * 80 + ub];
                float4 fA1 = *(float4*)&Ps[(rowA + 8) * 80 + ub];
                unsigned a0[4] = {FU(fA0.x), FU(fA1.x), FU(fA0.y), FU(fA1.y)};
                unsigned a1[4] = {FU(fA0.z), FU(fA1.z), FU(fA0.w), FU(fA1.w)};
#pragma unroll
                for (int nt = 0; nt < 8; nt++) {
                    int c = 8 * nt + ln4;
                    unsigned b0[2] = {FU(Vs[(ub + 0) * 70 + c]), FU(Vs[(ub + 1) * 70 + c])};
                    unsigned b1[2] = {FU(Vs[(ub + 2) * 70 + c]), FU(Vs[(ub + 3) * 70 + c])};
                    mma_tf32(o_acc[nt], a0, b0);
                    mma_tf32(o_acc[nt], a1, b1);
                }
            }
        }

        // ---- epilogue ----
        if (!split) {
            float inv0 = 1.f / l_run[0];
            float inv1 = 1.f / l_run[1];
            float* Og = g_O + ((size_t)b * SS + q0) * HH;
#pragma unroll
            for (int nt = 0; nt < 8; nt++) {
                float2 o0 = {o_acc[nt][0] * inv0, o_acc[nt][1] * inv0};
                float2 o1 = {o_acc[nt][2] * inv1, o_acc[nt][3] * inv1};
                *(float2*)&Og[rowA * HH + 8 * nt + 2 * qd]       = o0;
                *(float2*)&Og[(rowA + 8) * HH + 8 * nt + 2 * qd] = o1;
            }
        } else {
            size_t rbase = (size_t)b * SS + q0;
            float* Op = g_Opart + (size_t)part * NROW * HH + rbase * HH;
#pragma unroll
            for (int nt = 0; nt < 8; nt++) {
                float2 o0 = {o_acc[nt][0], o_acc[nt][1]};
                float2 o1 = {o_acc[nt][2], o_acc[nt][3]};
                *(float2*)&Op[rowA * HH + 8 * nt + 2 * qd]       = o0;
                *(float2*)&Op[(rowA + 8) * HH + 8 * nt + 2 * qd] = o1;
            }
            if (qd == 0) {   // (m,l) replicated across quad by the shuffles
                float* ML = g_ML + ((size_t)part * NROW + rbase) * 2;
                *(float2*)&ML[rowA * 2]       = make_float2(m_run[0], l_run[0]);
                *(float2*)&ML[(rowA + 8) * 2] = make_float2(m_run[1], l_run[1]);
            }
        }
    }
}

// ============================================================================
// Kernel 2b: merge split-KV partials.  Rows 1024..2047 (per batch): 2 parts,
// rows 2048..4095: 4 parts.  Exact softmax merge.
// ============================================================================
__global__ __launch_bounds__(128) void combine_kernel()
{
    int rid = blockIdx.x * 2 + (threadIdx.x >> 6);   // 2 rows per block
    int c = threadIdx.x & 63;
    int batch = rid / 3072;
    int r_in  = (rid % 3072) + 1024;
    size_t row = (size_t)batch * SS + r_in;
    int np = (r_in >= 2048) ? 4 : 2;

    float2 ml[4];
    float m = -1e30f;
#pragma unroll
    for (int p = 0; p < 4; p++) {
        if (p < np) {
            ml[p] = *(float2*)&g_ML[((size_t)p * NROW + row) * 2];
            m = fmaxf(m, ml[p].x);
        }
    }
    float num = 0.f, den = 0.f;
#pragma unroll
    for (int p = 0; p < 4; p++) {
        if (p < np) {
            float a = __expf(ml[p].x - m);
            den += ml[p].y * a;
            num += g_Opart[(size_t)p * NROW * HH + row * HH + c] * a;
        }
    }
    g_O[row * HH + c] = num / den;
}

// ============================================================================
// Kernel 3: output projection, tf32 mma.  256 thr / 8 warps, M 128, N 64, K 64.
// ============================================================================
__global__ __launch_bounds__(256) void outproj_tf32_kernel(
    const float* __restrict__ Wo, const float* __restrict__ bo,
    float* __restrict__ out)
{
    extern __shared__ float sm[];
    float* Os = sm;              // 128 x 80
    float* Ws = sm + 128 * 80;   // 64 x 70

    const int row0 = blockIdx.x * 128, n0 = blockIdx.y * 64;
    const int t = threadIdx.x, w = t >> 5, lane = t & 31;
    const int qd = lane & 3, ln4 = lane >> 2;
    const int rowA = 16 * w + ln4;

#pragma unroll
    for (int l = 0; l < 8; l++) {
        int u = t + l * 256, r = u >> 4, c4 = u & 15;
        float4 v = *(const float4*)(g_O + (size_t)(row0 + r) * HH + c4 * 4);
        v.x = rne(v.x); v.y = rne(v.y); v.z = rne(v.z); v.w = rne(v.w);
        *(float4*)&Os[r * 80 + c4 * 4] = v;
    }
#pragma unroll
    for (int l = 0; l < 4; l++) {
        int u = t + l * 256, kk = u >> 4, c4 = u & 15;
        float4 v = *(const float4*)(Wo + (size_t)kk * DD + n0 + c4 * 4);
        float2 lo = {rne(v.x), rne(v.y)}, hi = {rne(v.z), rne(v.w)};
        *(float2*)&Ws[kk * 70 + c4 * 4]     = lo;
        *(float2*)&Ws[kk * 70 + c4 * 4 + 2] = hi;
    }
    __syncthreads();

    float acc[8][4];
#pragma unroll
    for (int nt = 0; nt < 8; nt++)
#pragma unroll
        for (int v = 0; v < 4; v++) acc[nt][v] = 0.f;

#pragma unroll
    for (int jj = 0; jj < 4; jj++) {
        int ub = (qd + 4 * jj) * 4;
        float4 f0 = *(float4*)&Os[rowA * 80 + ub];
        float4 f1 = *(float4*)&Os[(rowA + 8) * 80 + ub];
        unsigned a0[4] = {FU(f0.x), FU(f1.x), FU(f0.y), FU(f1.y)};
        unsigned a1[4] = {FU(f0.z), FU(f1.z), FU(f0.w), FU(f1.w)};
#pragma unroll
        for (int nt = 0; nt < 8; nt++) {
            int c = 8 * nt + ln4;
            unsigned b0[2] = {FU(Ws[(ub + 0) * 70 + c]), FU(Ws[(ub + 1) * 70 + c])};
            unsigned b1[2] = {FU(Ws[(ub + 2) * 70 + c]), FU(Ws[(ub + 3) * 70 + c])};
            mma_tf32(acc[nt], a0, b0);
            mma_tf32(acc[nt], a1, b1);
        }
    }

#pragma unroll
    for (int nt = 0; nt < 8; nt++) {
        int c = 8 * nt + 2 * qd;
        int row = row0 + rowA;
        float b0 = bo[n0 + c], b1 = bo[n0 + c + 1];
        float2 v0 = {acc[nt][0] + b0, acc[nt][1] + b1};
        float2 v1 = {acc[nt][2] + b0, acc[nt][3] + b1};
        *(float2*)(out + (size_t)row * DD + n0 + c)       = v0;
        *(float2*)(out + (size_t)(row + 8) * DD + n0 + c) = v1;
    }
}

// ============================================================================
extern "C" void kernel_launch(void* const* d_in, const int* in_sizes, int n_in,
                              void* d_out, int out_size)
{
    const float* x  = (const float*)d_in[0];
    const float* Wq = (const float*)d_in[1];
    const float* bq = (const float*)d_in[2];
    const float* Wk = (const float*)d_in[3];
    const float* bk = (const float*)d_in[4];
    const float* Wv = (const float*)d_in[5];
    const float* bv = (const float*)d_in[6];
    const float* Wo = (const float*)d_in[7];
    const float* bo = (const float*)d_in[8];
    float* out = (float*)d_out;

    const int proj_smem  = (128 * 80 + 64 * 70) * 4;     // 58880
    const int flash_smem = (3 * 64 * 80 + 64 * 70) * 4;  // 79360

    static int attr_set = 0;
    if (!attr_set) {
        cudaFuncSetAttribute(qkv_tf32_kernel,
                             cudaFuncAttributeMaxDynamicSharedMemorySize, proj_smem);
        cudaFuncSetAttribute(flash_tf32_kernel,
                             cudaFuncAttributeMaxDynamicSharedMemorySize, flash_smem);
        cudaFuncSetAttribute(outproj_tf32_kernel,
                             cudaFuncAttributeMaxDynamicSharedMemorySize, proj_smem);
        attr_set = 1;
    }

    qkv_tf32_kernel<<<dim3(NROW / 128, 3), 256, proj_smem>>>(x, Wq, bq, Wk, bk, Wv, bv);
    flash_tf32_kernel<<<296, 128, flash_smem>>>();
    combine_kernel<<<(BB * 3072) / 2, 128>>>();
    outproj_tf32_kernel<<<dim3(NROW / 128, DD / 64), 256, proj_smem>>>(Wo, bo, out);
}